// round 8
// baseline (speedup 1.0000x reference)
#include <cuda_runtime.h>
#include <cuda_bf16.h>
#include <cstdint>

#define NSTR   4
#define T_LEN  8192
#define D_HID  2048
#define ND     8192
#define NOUT   24
#define NACC   25
#define KC     64
#define NSLOT  8                 // 4 segments x 2 k-halves
#define NT2    16                // tiles per CTA (k = 1024)
#define WELEM  1728              // 24 rows * 72 bf16 per packed W tile
#define WB     3456              // bytes per packed W tile

// smem layout (bytes from 1024-aligned base tb)
#define A_SLOT    16384          // bf16 A tile: 128 rows x 128B (SW128)
#define B_OFF     32768          // 3 x 3456
#define X_OFF     43136          // 2 x 34816 (128 rows x 272B fp32)
#define X_SLOT    34816
#define X_STRIDE  272
#define SMEM_DYN  (1024 + 43136 + 2 * X_SLOT)   // 113,792 + pad

// packed bf16 weights: [s*32 + tile][24 rows][72 (64 data + 8 pad)]
__device__ __align__(16) __nv_bfloat16 g_w[NSTR * 32 * WELEM];
// partials: [slot][acc][row]
__device__ float g_scratch[NSLOT][NACC][T_LEN];

__device__ __forceinline__ uint32_t sw128(uint32_t o) {
    return o ^ ((o >> 3) & 0x70u);
}
__device__ __forceinline__ uint32_t cvt2(float lo, float hi) {
    uint32_t r;
    asm("cvt.rn.bf16x2.f32 %0, %1, %2;" : "=r"(r) : "f"(hi), "f"(lo));
    return r;
}
__device__ __forceinline__ float4 lds128f(uint32_t a) {
    float4 v;
    asm volatile("ld.shared.v4.f32 {%0,%1,%2,%3}, [%4];"
                 : "=f"(v.x), "=f"(v.y), "=f"(v.z), "=f"(v.w) : "r"(a));
    return v;
}
__device__ __forceinline__ void sts128(uint32_t a, uint32_t x, uint32_t y,
                                       uint32_t z, uint32_t w) {
    asm volatile("st.shared.v4.b32 [%0], {%1,%2,%3,%4};"
                 :: "r"(a), "r"(x), "r"(y), "r"(z), "r"(w) : "memory");
}
__device__ __forceinline__ uint32_t lds32(uint32_t a) {
    uint32_t v;
    asm volatile("ld.shared.b32 %0, [%1];" : "=r"(v) : "r"(a));
    return v;
}
__device__ __forceinline__ void cp16(uint32_t dst, const void* src) {
    asm volatile("cp.async.cg.shared.global [%0], [%1], 16;" :: "r"(dst), "l"(src) : "memory");
}
__device__ __forceinline__ void cp_commit() {
    asm volatile("cp.async.commit_group;" ::: "memory");
}
template <int N> __device__ __forceinline__ void cp_wait() {
    asm volatile("cp.async.wait_group %0;" :: "n"(N) : "memory");
}
__device__ __forceinline__ void ldsm4(uint32_t* r, uint32_t addr) {
    asm volatile("ldmatrix.sync.aligned.m8n8.x4.shared.b16 {%0,%1,%2,%3}, [%4];"
                 : "=r"(r[0]), "=r"(r[1]), "=r"(r[2]), "=r"(r[3]) : "r"(addr));
}
__device__ __forceinline__ void mma4(float* d, const uint32_t* a,
                                     uint32_t b0, uint32_t b1) {
    asm volatile(
        "mma.sync.aligned.m16n8k16.row.col.f32.bf16.bf16.f32 "
        "{%0,%1,%2,%3}, {%4,%5,%6,%7}, {%8,%9}, {%0,%1,%2,%3};"
        : "+f"(d[0]), "+f"(d[1]), "+f"(d[2]), "+f"(d[3])
        : "r"(a[0]), "r"(a[1]), "r"(a[2]), "r"(a[3]), "r"(b0), "r"(b1));
}

// ---- W pack (vectorized): bf16, [24][72] rows per (s,tile) ----
__global__ void mhc_prep(const float* __restrict__ Wpre,
                         const float* __restrict__ Wpost,
                         const float* __restrict__ Wres)
{
    const int id  = blockIdx.x * 256 + threadIdx.x;   // 0..49151
    const int k4  = id & 15;                          // 16B chunk within 64-k tile
    const int j   = (id >> 4) % 24;
    const int st  = (id >> 4) / 24;                   // s*32 + tile
    const int s   = st >> 5, tile = st & 31;

    const int kg = s * D_HID + tile * KC + k4 * 4;
    const float* src;
    if (j < 4)      src = Wpre  + (size_t)j       * ND + kg;
    else if (j < 8) src = Wpost + (size_t)(j - 4) * ND + kg;
    else            src = Wres  + (size_t)(j - 8) * ND + kg;
    const float4 v = *reinterpret_cast<const float4*>(src);

    uint2 o;
    o.x = cvt2(v.x, v.y);
    o.y = cvt2(v.z, v.w);
    *reinterpret_cast<uint2*>(
        reinterpret_cast<unsigned char*>(g_w) +
        (size_t)st * WB + j * 144 + k4 * 8) = o;
}

extern __shared__ unsigned char dsm[];

__global__ __launch_bounds__(256, 2)
void mhc_main_mma(const float* __restrict__ stream)
{
    const int tid  = threadIdx.x;
    const int w    = tid >> 5, lane = tid & 31;
    const int g    = lane >> 3, c = lane & 7;       // convert mapping
    const int g4   = lane >> 2, t4 = lane & 3;      // mma B-frag mapping
    const int rb   = blockIdx.x & 63;
    const int s2   = blockIdx.x >> 6;               // slot 0..7
    const int s    = s2 >> 1;
    const int half = s2 & 1;
    const int R    = rb * 128;

    const uint32_t raw = (uint32_t)__cvta_generic_to_shared(dsm);
    const uint32_t tb  = (raw + 1023u) & ~1023u;
    const uint32_t bsb = tb + B_OFF;
    const uint32_t xsb = tb + X_OFF;

    const float* xbase = stream + ((size_t)s * T_LEN + R) * D_HID + half * 1024;

    int rr[4];
#pragma unroll
    for (int p = 0; p < 4; p++) rr[p] = p * 32 + w * 4 + g;
    const int q7 = (w * 4 + g) & 7;
    const int cc = c ^ q7;                 // conflict-free chunk remap

    // ldmatrix per-thread A offset (quadrant order)
    const int qq   = lane >> 3;
    const int arow = w * 16 + (qq & 1) * 8 + (lane & 7);
    const uint32_t aoff = (uint32_t)(arow * 128 + (qq >> 1) * 16);

    // B fragment base offset (row stride 144B)
    const uint32_t boffbase = (uint32_t)(g4 * 144 + t4 * 4);

    float acc[3][4];
#pragma unroll
    for (int j = 0; j < 3; j++)
#pragma unroll
        for (int i = 0; i < 4; i++) acc[j][i] = 0.f;
    float ss[4] = {0.f, 0.f, 0.f, 0.f};

    // X staging addresses (thread stages rows (tid>>4)+16i, chunk tid&15)
    const uint32_t xdst0 = xsb + (uint32_t)((tid >> 4) * X_STRIDE + (tid & 15) * 16);
    const float*   xsrc0 = xbase + (size_t)(tid >> 4) * D_HID + (tid & 15) * 4;

    auto stage_x = [&](int u, int slot) {
        const uint32_t d0 = xdst0 + (uint32_t)slot * X_SLOT;
        const float*   s0 = xsrc0 + u * KC;
#pragma unroll
        for (int i = 0; i < 8; i++)
            cp16(d0 + i * 16 * X_STRIDE, s0 + (size_t)i * 16 * D_HID);
    };
    auto stage_b = [&](int u, int slot) {
        if (tid < 216)
            cp16(bsb + (uint32_t)slot * WB + tid * 16,
                 reinterpret_cast<const unsigned char*>(g_w) +
                     (size_t)(s * 32 + half * NT2 + u) * WB + tid * 16);
    };
    auto convert = [&](int u) {
        const uint32_t xs = xsb + (uint32_t)(u & 1) * X_SLOT;
        const uint32_t ab = tb + (uint32_t)(u & 1) * A_SLOT;
#pragma unroll
        for (int p = 0; p < 4; p++) {
            const int r = rr[p];
            const uint32_t rd = xs + (uint32_t)(r * X_STRIDE + cc * 32);
            const float4 q0 = lds128f(rd);
            const float4 q1 = lds128f(rd + 16);
            sts128(ab + sw128((uint32_t)(r * 128 + cc * 16)),
                   cvt2(q0.x, q0.y), cvt2(q0.z, q0.w),
                   cvt2(q1.x, q1.y), cvt2(q1.z, q1.w));
            ss[p] = fmaf(q0.x, q0.x, fmaf(q0.y, q0.y,
                     fmaf(q0.z, q0.z, fmaf(q0.w, q0.w,
                     fmaf(q1.x, q1.x, fmaf(q1.y, q1.y,
                     fmaf(q1.z, q1.z, fmaf(q1.w, q1.w, ss[p]))))))));
        }
    };
    auto compute = [&](int t) {
        const uint32_t ab = tb + (uint32_t)(t & 1) * A_SLOT;
        const uint32_t bb = bsb + (uint32_t)(t % 3) * WB;
#pragma unroll
        for (int kc = 0; kc < 4; kc++) {
            uint32_t ah[4];
            ldsm4(ah, ab + sw128(aoff + kc * 32));
#pragma unroll
            for (int j = 0; j < 3; j++) {
                const uint32_t bo = bb + boffbase + (uint32_t)(j * 8 * 144 + kc * 32);
                mma4(acc[j], ah, lds32(bo), lds32(bo + 16));
            }
        }
    };

    // ---- prologue: tiles 0 and 1 in flight ----
    stage_x(0, 0); stage_b(0, 0); cp_commit();
    stage_x(1, 1); stage_b(1, 1); cp_commit();
    cp_wait<1>();
    convert(0);
    __syncthreads();

    // ---- mainloop: one barrier per tile ----
    for (int t = 0; t < NT2; ++t) {
        if (t + 2 < NT2) {
            stage_x(t + 2, t & 1);          // tile u -> X slot u%2
            stage_b(t + 2, (t + 2) % 3);    // tile u -> B slot u%3
        }
        cp_commit();                         // group G_t (may be empty)
        cp_wait<1>();                        // G_{t-1} done: X(t+1), B(t+1)
        if (t + 1 < NT2) convert(t + 1);     // Xs[(t+1)%2] -> A[(t+1)%2]
        compute(t);                          // A[t%2], B[t%3]
        __syncthreads();
    }

    // ---- sumsq: reduce over the 8 c-lanes per row ----
#pragma unroll
    for (int p = 0; p < 4; p++) {
        float v = ss[p];
        v += __shfl_down_sync(0xffffffffu, v, 4, 8);
        v += __shfl_down_sync(0xffffffffu, v, 2, 8);
        v += __shfl_down_sync(0xffffffffu, v, 1, 8);
        if (c == 0) g_scratch[s2][24][R + rr[p]] = v;
    }

    // ---- write dot partials: warp w owns rows R + w*16 .. +15 ----
    const int row0 = R + w * 16 + g4;
#pragma unroll
    for (int j = 0; j < 3; j++) {
        const int col = j * 8 + t4 * 2;
        g_scratch[s2][col    ][row0]     = acc[j][0];
        g_scratch[s2][col + 1][row0]     = acc[j][1];
        g_scratch[s2][col    ][row0 + 8] = acc[j][2];
        g_scratch[s2][col + 1][row0 + 8] = acc[j][3];
    }
}

__global__ __launch_bounds__(64)
void mhc_epilogue(const float* __restrict__ bpre,
                  const float* __restrict__ bpost,
                  const float* __restrict__ bres,
                  const float* __restrict__ apre_p,
                  const float* __restrict__ apost_p,
                  const float* __restrict__ ares_p,
                  float* __restrict__ out)
{
    const int t = blockIdx.x * 64 + threadIdx.x;

    float v[NACC];
#pragma unroll
    for (int i = 0; i < NACC; i++) {
        float a = 0.f;
#pragma unroll
        for (int sl = 0; sl < NSLOT; sl++) a += g_scratch[sl][i][t];
        v[i] = a;
    }

    const float rn = rsqrtf(v[24] * (1.0f / (float)ND) + 1e-8f);

    const float apre  = *apre_p;
    const float apost = *apost_p;
    const float ares  = *ares_p;

    float* outres  = out;                          // (T,4,4)
    float* outpre  = out + (size_t)T_LEN * 16;     // (T,4)
    float* outpost = out + (size_t)T_LEN * 20;     // (T,4)

#pragma unroll
    for (int k = 0; k < 4; k++) {
        const float z = apre * v[k] * rn + bpre[k];
        outpre[(size_t)t * 4 + k] = __fdividef(1.0f, 1.0f + __expf(-z));
    }
#pragma unroll
    for (int k = 0; k < 4; k++) {
        const float z = apost * v[4 + k] * rn + bpost[k];
        outpost[(size_t)t * 4 + k] = __fdividef(2.0f, 1.0f + __expf(-z));
    }

    float M[16];
#pragma unroll
    for (int i = 0; i < 16; i++)
        M[i] = __expf(ares * v[8 + i] * rn + bres[i]);

    for (int it = 0; it < 20; it++) {
#pragma unroll
        for (int a = 0; a < 4; a++) {
            const float r = __fdividef(1.0f,
                M[4*a] + M[4*a+1] + M[4*a+2] + M[4*a+3]);
            M[4*a] *= r; M[4*a+1] *= r; M[4*a+2] *= r; M[4*a+3] *= r;
        }
#pragma unroll
        for (int b = 0; b < 4; b++) {
            const float r = __fdividef(1.0f,
                M[b] + M[4+b] + M[8+b] + M[12+b]);
            M[b] *= r; M[4+b] *= r; M[8+b] *= r; M[12+b] *= r;
        }
    }
#pragma unroll
    for (int i = 0; i < 16; i++) outres[(size_t)t * 16 + i] = M[i];
}

extern "C" void kernel_launch(void* const* d_in, const int* in_sizes, int n_in,
                              void* d_out, int out_size) {
    const float* stream = (const float*)d_in[0];
    const float* Wpre   = (const float*)d_in[1];
    const float* Wpost  = (const float*)d_in[2];
    const float* Wres   = (const float*)d_in[3];
    const float* bpre   = (const float*)d_in[4];
    const float* bpost  = (const float*)d_in[5];
    const float* bres   = (const float*)d_in[6];
    const float* apre   = (const float*)d_in[7];
    const float* apost  = (const float*)d_in[8];
    const float* ares   = (const float*)d_in[9];

    cudaFuncSetAttribute(mhc_main_mma,
                         cudaFuncAttributeMaxDynamicSharedMemorySize, SMEM_DYN);

    mhc_prep<<<192, 256>>>(Wpre, Wpost, Wres);
    mhc_main_mma<<<512, 256, SMEM_DYN>>>(stream);
    mhc_epilogue<<<T_LEN / 64, 64>>>(bpre, bpost, bres, apre, apost, ares,
                                     (float*)d_out);
}

// round 9
// speedup vs baseline: 1.1724x; 1.1724x over previous
#include <cuda_runtime.h>
#include <cuda_bf16.h>
#include <cstdint>

#define NSTR   4
#define T_LEN  8192
#define D_HID  2048
#define ND     8192
#define NOUT   24
#define NACC   25
#define KC     64
#define NSLOT  8                 // 4 segments x 2 k-halves
#define NT2    16                // tiles per CTA (k = 1024)
#define WELEM  1728              // 24 rows * 72 bf16 per packed W tile
#define WB     3456              // bytes per packed W tile

// per-buffer smem layout (bytes)
#define OFF_A  0
#define OFF_B  16384
#define BUF_BYTES 20480
#define SMEM_DYN (1024 + 2 * BUF_BYTES)   // 41,984 -> 4 CTAs/SM fits 228KB

// packed bf16 weights: [s*32 + tile][24 rows][72 (64 data + 8 pad)]
__device__ __align__(16) __nv_bfloat16 g_w[NSTR * 32 * WELEM];
// partials: [slot][acc][row]
__device__ float g_scratch[NSLOT][NACC][T_LEN];

__device__ __forceinline__ uint32_t sw128(uint32_t o) {
    return o ^ ((o >> 3) & 0x70u);
}
__device__ __forceinline__ uint32_t cvt2(float lo, float hi) {
    uint32_t r;
    asm("cvt.rn.bf16x2.f32 %0, %1, %2;" : "=r"(r) : "f"(hi), "f"(lo));
    return r;
}
__device__ __forceinline__ void sts64(uint32_t a, uint32_t x, uint32_t y) {
    asm volatile("st.shared.v2.b32 [%0], {%1, %2};" :: "r"(a), "r"(x), "r"(y) : "memory");
}
__device__ __forceinline__ uint32_t lds32(uint32_t a) {
    uint32_t v;
    asm volatile("ld.shared.b32 %0, [%1];" : "=r"(v) : "r"(a));
    return v;
}
__device__ __forceinline__ void cp16(uint32_t dst, const void* src) {
    asm volatile("cp.async.cg.shared.global [%0], [%1], 16;" :: "r"(dst), "l"(src) : "memory");
}
__device__ __forceinline__ void cp_commit() {
    asm volatile("cp.async.commit_group;" ::: "memory");
}
template <int N> __device__ __forceinline__ void cp_wait() {
    asm volatile("cp.async.wait_group %0;" :: "n"(N) : "memory");
}
__device__ __forceinline__ void ldsm4(uint32_t* r, uint32_t addr) {
    asm volatile("ldmatrix.sync.aligned.m8n8.x4.shared.b16 {%0,%1,%2,%3}, [%4];"
                 : "=r"(r[0]), "=r"(r[1]), "=r"(r[2]), "=r"(r[3]) : "r"(addr));
}
__device__ __forceinline__ void mma4(float* d, const uint32_t* a,
                                     uint32_t b0, uint32_t b1) {
    asm volatile(
        "mma.sync.aligned.m16n8k16.row.col.f32.bf16.bf16.f32 "
        "{%0,%1,%2,%3}, {%4,%5,%6,%7}, {%8,%9}, {%0,%1,%2,%3};"
        : "+f"(d[0]), "+f"(d[1]), "+f"(d[2]), "+f"(d[3])
        : "r"(a[0]), "r"(a[1]), "r"(a[2]), "r"(a[3]), "r"(b0), "r"(b1));
}

// ---- W pack (vectorized): bf16, [24][72] rows per (s,tile) ----
__global__ void mhc_prep(const float* __restrict__ Wpre,
                         const float* __restrict__ Wpost,
                         const float* __restrict__ Wres)
{
    const int id  = blockIdx.x * 256 + threadIdx.x;   // 0..49151
    const int k4  = id & 15;                          // 16B chunk within 64-k tile
    const int j   = (id >> 4) % 24;
    const int st  = (id >> 4) / 24;                   // s*32 + tile
    const int s   = st >> 5, tile = st & 31;

    const int kg = s * D_HID + tile * KC + k4 * 4;
    const float* src;
    if (j < 4)      src = Wpre  + (size_t)j       * ND + kg;
    else if (j < 8) src = Wpost + (size_t)(j - 4) * ND + kg;
    else            src = Wres  + (size_t)(j - 8) * ND + kg;
    const float4 v = *reinterpret_cast<const float4*>(src);

    uint2 o;
    o.x = cvt2(v.x, v.y);
    o.y = cvt2(v.z, v.w);
    *reinterpret_cast<uint2*>(
        reinterpret_cast<unsigned char*>(g_w) +
        (size_t)st * WB + j * 144 + k4 * 8) = o;
}

extern __shared__ unsigned char dsm[];

__global__ __launch_bounds__(256, 4)
void mhc_main_mma(const float* __restrict__ stream)
{
    const int tid  = threadIdx.x;
    const int w    = tid >> 5, lane = tid & 31;
    const int g    = lane >> 3, c = lane & 7;       // X-load mapping
    const int g4   = lane >> 2, t4 = lane & 3;      // mma B-frag mapping
    const int rb   = blockIdx.x & 63;
    const int s2   = blockIdx.x >> 6;               // slot 0..7
    const int s    = s2 >> 1;
    const int half = s2 & 1;
    const int R    = rb * 128;

    const uint32_t raw = (uint32_t)__cvta_generic_to_shared(dsm);
    const uint32_t tb  = (raw + 1023u) & ~1023u;

    const float* xbase = stream + ((size_t)s * T_LEN + R) * D_HID + half * 1024;

    int rr[4];
#pragma unroll
    for (int p = 0; p < 4; p++) rr[p] = p * 32 + w * 4 + g;

    // ldmatrix per-thread A offset (quadrant order)
    const int q    = lane >> 3;
    const int arow = w * 16 + (q & 1) * 8 + (lane & 7);
    const uint32_t aoff = (uint32_t)(arow * 128 + (q >> 1) * 16);

    // B fragment base offset (row stride 144B)
    const uint32_t boffbase = (uint32_t)(g4 * 144 + t4 * 4);

    float acc[3][4];
#pragma unroll
    for (int j = 0; j < 3; j++)
#pragma unroll
        for (int i = 0; i < 4; i++) acc[j][i] = 0.f;
    float ss[4] = {0.f, 0.f, 0.f, 0.f};

    float4 xr[4];    // half of the X tile rows (registers reused)

    auto ldx = [&](int t, int h) {
#pragma unroll
        for (int pp = 0; pp < 2; pp++)
#pragma unroll
            for (int u = 0; u < 2; u++)
                xr[pp * 2 + u] = *reinterpret_cast<const float4*>(
                    xbase + (size_t)rr[2 * h + pp] * D_HID + t * KC + (c * 2 + u) * 4);
    };
    auto stx = [&](int b, int h) {
        const uint32_t bufb = tb + (uint32_t)b * BUF_BYTES;
#pragma unroll
        for (int pp = 0; pp < 2; pp++) {
            const int p = 2 * h + pp;
#pragma unroll
            for (int u = 0; u < 2; u++) {
                const float4 qv = xr[pp * 2 + u];
                const uint32_t h01 = cvt2(qv.x, qv.y);
                const uint32_t h23 = cvt2(qv.z, qv.w);
                const uint32_t off = sw128((uint32_t)(rr[p] * 128 + (c * 2 + u) * 8));
                sts64(bufb + OFF_A + off, h01, h23);
                ss[p] = fmaf(qv.x, qv.x, fmaf(qv.y, qv.y,
                         fmaf(qv.z, qv.z, fmaf(qv.w, qv.w, ss[p]))));
            }
        }
    };
    auto stage_b = [&](int t, int b) {
        if (tid < 216) {
            const size_t base = (size_t)(s * 32 + half * NT2 + t) * WELEM;
            cp16(tb + (uint32_t)b * BUF_BYTES + OFF_B + tid * 16,
                 (const unsigned char*)g_w + base * 2 + tid * 16);
        }
    };
    auto compute_kc = [&](uint32_t bufb, int kc) {
        uint32_t ah[4];
        ldsm4(ah, bufb + OFF_A + sw128(aoff + kc * 32));
#pragma unroll
        for (int j = 0; j < 3; j++) {
            const uint32_t bo = bufb + OFF_B + boffbase
                              + (uint32_t)(j * 8 * 144 + kc * 32);
            mma4(acc[j], ah, lds32(bo), lds32(bo + 16));
        }
    };

    // ---- prologue: tile 0 into buffer 0 ----
    ldx(0, 0); stage_b(0, 0); stx(0, 0);
    ldx(0, 1); stx(0, 1);
    cp_commit();
    cp_wait<0>();
    __syncthreads();

    // ---- mainloop ----
    for (int t = 0; t < NT2; ++t) {
        const int b = t & 1;
        const uint32_t bufb = tb + (uint32_t)b * BUF_BYTES;
        const bool pre = (t + 1 < NT2);

        if (pre) { stage_b(t + 1, b ^ 1); ldx(t + 1, 0); }
        compute_kc(bufb, 0);
        compute_kc(bufb, 1);
        if (pre) { stx(b ^ 1, 0); ldx(t + 1, 1); }
        compute_kc(bufb, 2);
        compute_kc(bufb, 3);
        if (pre) stx(b ^ 1, 1);
        cp_commit();
        cp_wait<0>();
        __syncthreads();
    }

    // ---- sumsq: reduce over the 8 c-lanes per row ----
#pragma unroll
    for (int p = 0; p < 4; p++) {
        float v = ss[p];
        v += __shfl_down_sync(0xffffffffu, v, 4, 8);
        v += __shfl_down_sync(0xffffffffu, v, 2, 8);
        v += __shfl_down_sync(0xffffffffu, v, 1, 8);
        if (c == 0) g_scratch[s2][24][R + rr[p]] = v;
    }

    // ---- write dot partials: warp w owns rows R + w*16 .. +15 ----
    const int row0 = R + w * 16 + g4;
#pragma unroll
    for (int j = 0; j < 3; j++) {
        const int col = j * 8 + t4 * 2;
        g_scratch[s2][col    ][row0]     = acc[j][0];
        g_scratch[s2][col + 1][row0]     = acc[j][1];
        g_scratch[s2][col    ][row0 + 8] = acc[j][2];
        g_scratch[s2][col + 1][row0 + 8] = acc[j][3];
    }
}

__global__ __launch_bounds__(128)
void mhc_epilogue(const float* __restrict__ bpre,
                  const float* __restrict__ bpost,
                  const float* __restrict__ bres,
                  const float* __restrict__ apre_p,
                  const float* __restrict__ apost_p,
                  const float* __restrict__ ares_p,
                  float* __restrict__ out)
{
    const int t = blockIdx.x * 128 + threadIdx.x;

    float v[NACC];
#pragma unroll
    for (int i = 0; i < NACC; i++) {
        float a = 0.f;
#pragma unroll
        for (int sl = 0; sl < NSLOT; sl++) a += g_scratch[sl][i][t];
        v[i] = a;
    }

    const float rn = rsqrtf(v[24] * (1.0f / (float)ND) + 1e-8f);

    const float apre  = *apre_p;
    const float apost = *apost_p;
    const float ares  = *ares_p;

    float* outres  = out;                          // (T,4,4)
    float* outpre  = out + (size_t)T_LEN * 16;     // (T,4)
    float* outpost = out + (size_t)T_LEN * 20;     // (T,4)

#pragma unroll
    for (int k = 0; k < 4; k++) {
        const float z = apre * v[k] * rn + bpre[k];
        outpre[(size_t)t * 4 + k] = __fdividef(1.0f, 1.0f + __expf(-z));
    }
#pragma unroll
    for (int k = 0; k < 4; k++) {
        const float z = apost * v[4 + k] * rn + bpost[k];
        outpost[(size_t)t * 4 + k] = __fdividef(2.0f, 1.0f + __expf(-z));
    }

    float M[16];
#pragma unroll
    for (int i = 0; i < 16; i++)
        M[i] = __expf(ares * v[8 + i] * rn + bres[i]);

    for (int it = 0; it < 20; it++) {
#pragma unroll
        for (int a = 0; a < 4; a++) {
            const float r = __fdividef(1.0f,
                M[4*a] + M[4*a+1] + M[4*a+2] + M[4*a+3]);
            M[4*a] *= r; M[4*a+1] *= r; M[4*a+2] *= r; M[4*a+3] *= r;
        }
#pragma unroll
        for (int b = 0; b < 4; b++) {
            const float r = __fdividef(1.0f,
                M[b] + M[4+b] + M[8+b] + M[12+b]);
            M[b] *= r; M[4+b] *= r; M[8+b] *= r; M[12+b] *= r;
        }
    }
#pragma unroll
    for (int i = 0; i < 16; i++) outres[(size_t)t * 16 + i] = M[i];
}

extern "C" void kernel_launch(void* const* d_in, const int* in_sizes, int n_in,
                              void* d_out, int out_size) {
    const float* stream = (const float*)d_in[0];
    const float* Wpre   = (const float*)d_in[1];
    const float* Wpost  = (const float*)d_in[2];
    const float* Wres   = (const float*)d_in[3];
    const float* bpre   = (const float*)d_in[4];
    const float* bpost  = (const float*)d_in[5];
    const float* bres   = (const float*)d_in[6];
    const float* apre   = (const float*)d_in[7];
    const float* apost  = (const float*)d_in[8];
    const float* ares   = (const float*)d_in[9];

    cudaFuncSetAttribute(mhc_main_mma,
                         cudaFuncAttributeMaxDynamicSharedMemorySize, SMEM_DYN);

    mhc_prep<<<192, 256>>>(Wpre, Wpost, Wres);
    mhc_main_mma<<<512, 256, SMEM_DYN>>>(stream);
    mhc_epilogue<<<T_LEN / 128, 128>>>(bpre, bpost, bres, apre, apost, ares,
                                       (float*)d_out);
}

// round 10
// speedup vs baseline: 1.1844x; 1.0102x over previous
#include <cuda_runtime.h>
#include <cuda_bf16.h>
#include <cstdint>

#define NSTR   4
#define T_LEN  8192
#define D_HID  2048
#define ND     8192
#define NOUT   24
#define NACC   25
#define KC     64
#define NSLOT  8                 // 4 segments x 2 k-halves
#define NT2    16                // tiles per CTA (k = 1024)
#define WELEM  1728              // 24 rows * 72 bf16 per packed W tile
#define WB     3456              // bytes per packed W tile

// smem layout (bytes from 1024-aligned base tb)
#define A_SLOT    16384          // bf16 A tile: 128 rows x 128B (SW128), x2
#define B_OFF     32768          // 3 x 3456 B ring
#define SMEM_DYN  (1024 + 32768 + 3 * WB + 256)

// packed bf16 weights: [s*32 + tile][24 rows][72 (64 data + 8 pad)]
__device__ __align__(16) __nv_bfloat16 g_w[NSTR * 32 * WELEM];
// partials: [slot][acc][row]
__device__ float g_scratch[NSLOT][NACC][T_LEN];

__device__ __forceinline__ uint32_t sw128(uint32_t o) {
    return o ^ ((o >> 3) & 0x70u);
}
__device__ __forceinline__ uint32_t cvt2(float lo, float hi) {
    uint32_t r;
    asm("cvt.rn.bf16x2.f32 %0, %1, %2;" : "=r"(r) : "f"(hi), "f"(lo));
    return r;
}
__device__ __forceinline__ void sts64(uint32_t a, uint32_t x, uint32_t y) {
    asm volatile("st.shared.v2.b32 [%0], {%1, %2};" :: "r"(a), "r"(x), "r"(y) : "memory");
}
__device__ __forceinline__ uint32_t lds32(uint32_t a) {
    uint32_t v;
    asm volatile("ld.shared.b32 %0, [%1];" : "=r"(v) : "r"(a));
    return v;
}
__device__ __forceinline__ void cp16(uint32_t dst, const void* src) {
    asm volatile("cp.async.cg.shared.global [%0], [%1], 16;" :: "r"(dst), "l"(src) : "memory");
}
__device__ __forceinline__ void cp_commit() {
    asm volatile("cp.async.commit_group;" ::: "memory");
}
template <int N> __device__ __forceinline__ void cp_wait() {
    asm volatile("cp.async.wait_group %0;" :: "n"(N) : "memory");
}
__device__ __forceinline__ void ldsm4(uint32_t* r, uint32_t addr) {
    asm volatile("ldmatrix.sync.aligned.m8n8.x4.shared.b16 {%0,%1,%2,%3}, [%4];"
                 : "=r"(r[0]), "=r"(r[1]), "=r"(r[2]), "=r"(r[3]) : "r"(addr));
}
__device__ __forceinline__ void mma4(float* d, const uint32_t* a,
                                     uint32_t b0, uint32_t b1) {
    asm volatile(
        "mma.sync.aligned.m16n8k16.row.col.f32.bf16.bf16.f32 "
        "{%0,%1,%2,%3}, {%4,%5,%6,%7}, {%8,%9}, {%0,%1,%2,%3};"
        : "+f"(d[0]), "+f"(d[1]), "+f"(d[2]), "+f"(d[3])
        : "r"(a[0]), "r"(a[1]), "r"(a[2]), "r"(a[3]), "r"(b0), "r"(b1));
}

// ---- W pack (vectorized): bf16, [24][72] rows per (s,tile) ----
__global__ void mhc_prep(const float* __restrict__ Wpre,
                         const float* __restrict__ Wpost,
                         const float* __restrict__ Wres)
{
    const int id  = blockIdx.x * 256 + threadIdx.x;   // 0..49151
    const int k4  = id & 15;                          // 16B chunk within 64-k tile
    const int j   = (id >> 4) % 24;
    const int st  = (id >> 4) / 24;                   // s*32 + tile
    const int s   = st >> 5, tile = st & 31;

    const int kg = s * D_HID + tile * KC + k4 * 4;
    const float* src;
    if (j < 4)      src = Wpre  + (size_t)j       * ND + kg;
    else if (j < 8) src = Wpost + (size_t)(j - 4) * ND + kg;
    else            src = Wres  + (size_t)(j - 8) * ND + kg;
    const float4 v = *reinterpret_cast<const float4*>(src);

    uint2 o;
    o.x = cvt2(v.x, v.y);
    o.y = cvt2(v.z, v.w);
    *reinterpret_cast<uint2*>(
        reinterpret_cast<unsigned char*>(g_w) +
        (size_t)st * WB + j * 144 + k4 * 8) = o;
}

extern __shared__ unsigned char dsm[];

__global__ __launch_bounds__(256, 4)
void mhc_main_mma(const float* __restrict__ stream)
{
    const int tid  = threadIdx.x;
    const int w    = tid >> 5, lane = tid & 31;
    const int g    = lane >> 3, c = lane & 7;       // X-load mapping
    const int g4   = lane >> 2, t4 = lane & 3;      // mma B-frag mapping
    const int rb   = blockIdx.x & 63;
    const int s2   = blockIdx.x >> 6;               // slot 0..7
    const int s    = s2 >> 1;
    const int half = s2 & 1;
    const int R    = rb * 128;

    const uint32_t raw = (uint32_t)__cvta_generic_to_shared(dsm);
    const uint32_t tb  = (raw + 1023u) & ~1023u;
    const uint32_t bsb = tb + B_OFF;

    const float* xbase = stream + ((size_t)s * T_LEN + R) * D_HID + half * 1024;

    int rr[4];
#pragma unroll
    for (int p = 0; p < 4; p++) rr[p] = p * 32 + w * 4 + g;

    // ldmatrix per-thread A offset (quadrant order)
    const int q    = lane >> 3;
    const int arow = w * 16 + (q & 1) * 8 + (lane & 7);
    const uint32_t aoff = (uint32_t)(arow * 128 + (q >> 1) * 16);

    // B fragment base offset (row stride 144B)
    const uint32_t boffbase = (uint32_t)(g4 * 144 + t4 * 4);

    float acc[3][4];
#pragma unroll
    for (int j = 0; j < 3; j++)
#pragma unroll
        for (int i = 0; i < 4; i++) acc[j][i] = 0.f;
    float ss[4] = {0.f, 0.f, 0.f, 0.f};

    float4 xr[4];    // half of an X tile (reused; lives across barriers)

    auto ldx = [&](int t, int h) {
#pragma unroll
        for (int pp = 0; pp < 2; pp++)
#pragma unroll
            for (int u = 0; u < 2; u++)
                xr[pp * 2 + u] = *reinterpret_cast<const float4*>(
                    xbase + (size_t)rr[2 * h + pp] * D_HID + t * KC + (c * 2 + u) * 4);
    };
    auto stx = [&](int b, int h) {
        const uint32_t ab = tb + (uint32_t)b * A_SLOT;
#pragma unroll
        for (int pp = 0; pp < 2; pp++) {
            const int p = 2 * h + pp;
#pragma unroll
            for (int u = 0; u < 2; u++) {
                const float4 qv = xr[pp * 2 + u];
                const uint32_t h01 = cvt2(qv.x, qv.y);
                const uint32_t h23 = cvt2(qv.z, qv.w);
                const uint32_t off = sw128((uint32_t)(rr[p] * 128 + (c * 2 + u) * 8));
                sts64(ab + off, h01, h23);
                ss[p] = fmaf(qv.x, qv.x, fmaf(qv.y, qv.y,
                         fmaf(qv.z, qv.z, fmaf(qv.w, qv.w, ss[p]))));
            }
        }
    };
    auto stage_b = [&](int t, int slot) {
        if (tid < 216) {
            const size_t base = (size_t)(s * 32 + half * NT2 + t) * WELEM;
            cp16(bsb + (uint32_t)slot * WB + tid * 16,
                 (const unsigned char*)g_w + base * 2 + tid * 16);
        }
    };
    auto compute_kc = [&](uint32_t ab, uint32_t bb, int kc) {
        uint32_t ah[4];
        ldsm4(ah, ab + sw128(aoff + kc * 32));
#pragma unroll
        for (int j = 0; j < 3; j++) {
            const uint32_t bo = bb + boffbase + (uint32_t)(j * 8 * 144 + kc * 32);
            mma4(acc[j], ah, lds32(bo), lds32(bo + 16));
        }
    };

    // ---- prologue ----
    stage_b(0, 0); cp_commit();
    stage_b(1, 1); cp_commit();
    ldx(0, 0); stx(0, 0);
    ldx(0, 1); stx(0, 1);
    ldx(1, 0);                    // X(1) half0, consumed mid-tile 0
    cp_wait<1>();                 // B(0) resident
    __syncthreads();

    // ---- mainloop: 3-slot B ring (distance 2), rotated X prefetch ----
    for (int t = 0; t < NT2; ++t) {
        const int b  = t & 1;
        const uint32_t ab = tb + (uint32_t)b * A_SLOT;
        const uint32_t bb = bsb + (uint32_t)(t % 3) * WB;
        const bool pre = (t + 1 < NT2);

        if (t + 2 < NT2) stage_b(t + 2, (t + 2) % 3);
        cp_commit();

        compute_kc(ab, bb, 0);
        compute_kc(ab, bb, 1);
        if (pre) { stx(b ^ 1, 0); ldx(t + 1, 1); }
        compute_kc(ab, bb, 2);
        compute_kc(ab, bb, 3);
        if (pre) {
            stx(b ^ 1, 1);
            if (t + 2 < NT2) ldx(t + 2, 0);   // long-distance prefetch
        }

        cp_wait<1>();             // B(t+1) resident; B(t+2) may be in flight
        __syncthreads();
    }

    // ---- sumsq: reduce over the 8 c-lanes per row ----
#pragma unroll
    for (int p = 0; p < 4; p++) {
        float v = ss[p];
        v += __shfl_down_sync(0xffffffffu, v, 4, 8);
        v += __shfl_down_sync(0xffffffffu, v, 2, 8);
        v += __shfl_down_sync(0xffffffffu, v, 1, 8);
        if (c == 0) g_scratch[s2][24][R + rr[p]] = v;
    }

    // ---- write dot partials: warp w owns rows R + w*16 .. +15 ----
    const int row0 = R + w * 16 + g4;
#pragma unroll
    for (int j = 0; j < 3; j++) {
        const int col = j * 8 + t4 * 2;
        g_scratch[s2][col    ][row0]     = acc[j][0];
        g_scratch[s2][col + 1][row0]     = acc[j][1];
        g_scratch[s2][col    ][row0 + 8] = acc[j][2];
        g_scratch[s2][col + 1][row0 + 8] = acc[j][3];
    }
}

__global__ __launch_bounds__(128)
void mhc_epilogue(const float* __restrict__ bpre,
                  const float* __restrict__ bpost,
                  const float* __restrict__ bres,
                  const float* __restrict__ apre_p,
                  const float* __restrict__ apost_p,
                  const float* __restrict__ ares_p,
                  float* __restrict__ out)
{
    const int t = blockIdx.x * 128 + threadIdx.x;

    float v[NACC];
#pragma unroll
    for (int i = 0; i < NACC; i++) {
        float a = 0.f;
#pragma unroll
        for (int sl = 0; sl < NSLOT; sl++) a += g_scratch[sl][i][t];
        v[i] = a;
    }

    const float rn = rsqrtf(v[24] * (1.0f / (float)ND) + 1e-8f);

    const float apre  = *apre_p;
    const float apost = *apost_p;
    const float ares  = *ares_p;

    float* outres  = out;                          // (T,4,4)
    float* outpre  = out + (size_t)T_LEN * 16;     // (T,4)
    float* outpost = out + (size_t)T_LEN * 20;     // (T,4)

#pragma unroll
    for (int k = 0; k < 4; k++) {
        const float z = apre * v[k] * rn + bpre[k];
        outpre[(size_t)t * 4 + k] = __fdividef(1.0f, 1.0f + __expf(-z));
    }
#pragma unroll
    for (int k = 0; k < 4; k++) {
        const float z = apost * v[4 + k] * rn + bpost[k];
        outpost[(size_t)t * 4 + k] = __fdividef(2.0f, 1.0f + __expf(-z));
    }

    float M[16];
#pragma unroll
    for (int i = 0; i < 16; i++)
        M[i] = __expf(ares * v[8 + i] * rn + bres[i]);

    for (int it = 0; it < 20; it++) {
#pragma unroll
        for (int a = 0; a < 4; a++) {
            const float r = __fdividef(1.0f,
                M[4*a] + M[4*a+1] + M[4*a+2] + M[4*a+3]);
            M[4*a] *= r; M[4*a+1] *= r; M[4*a+2] *= r; M[4*a+3] *= r;
        }
#pragma unroll
        for (int b = 0; b < 4; b++) {
            const float r = __fdividef(1.0f,
                M[b] + M[4+b] + M[8+b] + M[12+b]);
            M[b] *= r; M[4+b] *= r; M[8+b] *= r; M[12+b] *= r;
        }
    }
#pragma unroll
    for (int i = 0; i < 16; i++) outres[(size_t)t * 16 + i] = M[i];
}

extern "C" void kernel_launch(void* const* d_in, const int* in_sizes, int n_in,
                              void* d_out, int out_size) {
    const float* stream = (const float*)d_in[0];
    const float* Wpre   = (const float*)d_in[1];
    const float* Wpost  = (const float*)d_in[2];
    const float* Wres   = (const float*)d_in[3];
    const float* bpre   = (const float*)d_in[4];
    const float* bpost  = (const float*)d_in[5];
    const float* bres   = (const float*)d_in[6];
    const float* apre   = (const float*)d_in[7];
    const float* apost  = (const float*)d_in[8];
    const float* ares   = (const float*)d_in[9];

    cudaFuncSetAttribute(mhc_main_mma,
                         cudaFuncAttributeMaxDynamicSharedMemorySize, SMEM_DYN);

    mhc_prep<<<192, 256>>>(Wpre, Wpost, Wres);
    mhc_main_mma<<<512, 256, SMEM_DYN>>>(stream);
    mhc_epilogue<<<T_LEN / 128, 128>>>(bpre, bpost, bres, apre, apost, ares,
                                       (float*)d_out);
}

// round 11
// speedup vs baseline: 1.2922x; 1.0910x over previous
#include <cuda_runtime.h>
#include <cuda_bf16.h>
#include <cstdint>

#define NSTR   4
#define T_LEN  8192
#define D_HID  2048
#define ND     8192
#define NOUT   24
#define NACC   25
#define KC     64
#define NSLOT  8                 // 4 segments x 2 k-halves
#define NT2    16                // tiles per CTA (k = 1024)
#define WELEM  1728              // 24 rows * 72 bf16 per packed W tile
#define WB     3456              // bytes per packed W tile

// smem layout (bytes from 1024-aligned base tb)
#define A_SLOT    16384          // bf16 A tile: 128 rows x 128B (SW128), x2
#define B_OFF     32768          // 3 x 3456 B ring
#define SMEM_DYN  (1024 + 32768 + 3 * WB + 256)

// packed bf16 weights: [s*32 + tile][24 rows][72 (64 data + 8 pad)]
__device__ __align__(16) __nv_bfloat16 g_w[NSTR * 32 * WELEM];
// partials: [slot][acc][row]
__device__ float g_scratch[NSLOT][NACC][T_LEN];
// per-rowblock arrival counters (reset to 0 by the consumer -> replay-safe)
__device__ int g_cnt[64];

__device__ __forceinline__ uint32_t sw128(uint32_t o) {
    return o ^ ((o >> 3) & 0x70u);
}
__device__ __forceinline__ uint32_t cvt2(float lo, float hi) {
    uint32_t r;
    asm("cvt.rn.bf16x2.f32 %0, %1, %2;" : "=r"(r) : "f"(hi), "f"(lo));
    return r;
}
__device__ __forceinline__ void sts64(uint32_t a, uint32_t x, uint32_t y) {
    asm volatile("st.shared.v2.b32 [%0], {%1, %2};" :: "r"(a), "r"(x), "r"(y) : "memory");
}
__device__ __forceinline__ uint32_t lds32(uint32_t a) {
    uint32_t v;
    asm volatile("ld.shared.b32 %0, [%1];" : "=r"(v) : "r"(a));
    return v;
}
__device__ __forceinline__ void cp16(uint32_t dst, const void* src) {
    asm volatile("cp.async.cg.shared.global [%0], [%1], 16;" :: "r"(dst), "l"(src) : "memory");
}
__device__ __forceinline__ void cp_commit() {
    asm volatile("cp.async.commit_group;" ::: "memory");
}
template <int N> __device__ __forceinline__ void cp_wait() {
    asm volatile("cp.async.wait_group %0;" :: "n"(N) : "memory");
}
__device__ __forceinline__ void ldsm4(uint32_t* r, uint32_t addr) {
    asm volatile("ldmatrix.sync.aligned.m8n8.x4.shared.b16 {%0,%1,%2,%3}, [%4];"
                 : "=r"(r[0]), "=r"(r[1]), "=r"(r[2]), "=r"(r[3]) : "r"(addr));
}
__device__ __forceinline__ void mma4(float* d, const uint32_t* a,
                                     uint32_t b0, uint32_t b1) {
    asm volatile(
        "mma.sync.aligned.m16n8k16.row.col.f32.bf16.bf16.f32 "
        "{%0,%1,%2,%3}, {%4,%5,%6,%7}, {%8,%9}, {%0,%1,%2,%3};"
        : "+f"(d[0]), "+f"(d[1]), "+f"(d[2]), "+f"(d[3])
        : "r"(a[0]), "r"(a[1]), "r"(a[2]), "r"(a[3]), "r"(b0), "r"(b1));
}

// ---- W pack (vectorized): bf16, [24][72] rows per (s,tile) ----
__global__ void mhc_prep(const float* __restrict__ Wpre,
                         const float* __restrict__ Wpost,
                         const float* __restrict__ Wres)
{
    const int id  = blockIdx.x * 256 + threadIdx.x;   // 0..49151
    const int k4  = id & 15;
    const int j   = (id >> 4) % 24;
    const int st  = (id >> 4) / 24;                   // s*32 + tile
    const int s   = st >> 5, tile = st & 31;

    const int kg = s * D_HID + tile * KC + k4 * 4;
    const float* src;
    if (j < 4)      src = Wpre  + (size_t)j       * ND + kg;
    else if (j < 8) src = Wpost + (size_t)(j - 4) * ND + kg;
    else            src = Wres  + (size_t)(j - 8) * ND + kg;
    const float4 v = *reinterpret_cast<const float4*>(src);

    uint2 o;
    o.x = cvt2(v.x, v.y);
    o.y = cvt2(v.z, v.w);
    *reinterpret_cast<uint2*>(
        reinterpret_cast<unsigned char*>(g_w) +
        (size_t)st * WB + j * 144 + k4 * 8) = o;
}

extern __shared__ unsigned char dsm[];

__global__ __launch_bounds__(256, 4)
void mhc_main_mma(const float* __restrict__ stream,
                  const float* __restrict__ bpre,
                  const float* __restrict__ bpost,
                  const float* __restrict__ bres,
                  const float* __restrict__ apre_p,
                  const float* __restrict__ apost_p,
                  const float* __restrict__ ares_p,
                  float* __restrict__ out)
{
    const int tid  = threadIdx.x;
    const int w    = tid >> 5, lane = tid & 31;
    const int g    = lane >> 3, c = lane & 7;       // X-load mapping
    const int g4   = lane >> 2, t4 = lane & 3;      // mma B-frag mapping
    const int rb   = blockIdx.x & 63;
    const int s2   = blockIdx.x >> 6;               // slot 0..7
    const int s    = s2 >> 1;
    const int half = s2 & 1;
    const int R    = rb * 128;

    const uint32_t raw = (uint32_t)__cvta_generic_to_shared(dsm);
    const uint32_t tb  = (raw + 1023u) & ~1023u;
    const uint32_t bsb = tb + B_OFF;

    const float* xbase = stream + ((size_t)s * T_LEN + R) * D_HID + half * 1024;

    // per-warp A ownership: warp w owns rows w*16 .. w*16+15
    int rr[4];
#pragma unroll
    for (int p = 0; p < 4; p++) rr[p] = w * 16 + p * 4 + g;

    // ldmatrix per-thread A offset (quadrant order) — same 16 rows
    const int q    = lane >> 3;
    const int arow = w * 16 + (q & 1) * 8 + (lane & 7);
    const uint32_t aoff = (uint32_t)(arow * 128 + (q >> 1) * 16);

    // B fragment base offset (row stride 144B)
    const uint32_t boffbase = (uint32_t)(g4 * 144 + t4 * 4);

    float acc[3][4];
#pragma unroll
    for (int j = 0; j < 3; j++)
#pragma unroll
        for (int i = 0; i < 4; i++) acc[j][i] = 0.f;
    float ss[4] = {0.f, 0.f, 0.f, 0.f};

    float4 xr[4];    // half of an X tile (reused; lives across barriers)

    // X cols: float offset u*32 + c*4 (contiguous 128B per (p,u) LDG, nL=4)
    auto ldx = [&](int t, int h) {
#pragma unroll
        for (int pp = 0; pp < 2; pp++)
#pragma unroll
            for (int u = 0; u < 2; u++)
                xr[pp * 2 + u] = *reinterpret_cast<const float4*>(
                    xbase + (size_t)rr[2 * h + pp] * D_HID + t * KC + u * 32 + c * 4);
    };
    auto stx = [&](int b, int h) {
        const uint32_t ab = tb + (uint32_t)b * A_SLOT;
#pragma unroll
        for (int pp = 0; pp < 2; pp++) {
            const int p = 2 * h + pp;
#pragma unroll
            for (int u = 0; u < 2; u++) {
                const float4 qv = xr[pp * 2 + u];
                const uint32_t h01 = cvt2(qv.x, qv.y);
                const uint32_t h23 = cvt2(qv.z, qv.w);
                const uint32_t off = sw128((uint32_t)(rr[p] * 128 + u * 64 + c * 8));
                sts64(ab + off, h01, h23);
                ss[p] = fmaf(qv.x, qv.x, fmaf(qv.y, qv.y,
                         fmaf(qv.z, qv.z, fmaf(qv.w, qv.w, ss[p]))));
            }
        }
    };
    auto stage_b = [&](int t, int slot) {
        if (tid < 216) {
            const size_t base = (size_t)(s * 32 + half * NT2 + t) * WELEM;
            cp16(bsb + (uint32_t)slot * WB + tid * 16,
                 (const unsigned char*)g_w + base * 2 + tid * 16);
        }
    };
    auto compute_kc = [&](uint32_t ab, uint32_t bb, int kc) {
        uint32_t ah[4];
        ldsm4(ah, ab + sw128(aoff + kc * 32));
#pragma unroll
        for (int j = 0; j < 3; j++) {
            const uint32_t bo = bb + boffbase + (uint32_t)(j * 8 * 144 + kc * 32);
            mma4(acc[j], ah, lds32(bo), lds32(bo + 16));
        }
    };

    // ---- prologue ----
    stage_b(0, 0); cp_commit();
    stage_b(1, 1); cp_commit();
    ldx(0, 0); stx(0, 0);
    ldx(0, 1); stx(0, 1);
    ldx(1, 0);
    cp_wait<1>();                 // B(0) resident
    __syncthreads();

    // ---- mainloop: 3-slot B ring (distance 2), rotated X prefetch ----
    for (int t = 0; t < NT2; ++t) {
        const int b  = t & 1;
        const uint32_t ab = tb + (uint32_t)b * A_SLOT;
        const uint32_t bb = bsb + (uint32_t)(t % 3) * WB;
        const bool pre = (t + 1 < NT2);

        if (t + 2 < NT2) stage_b(t + 2, (t + 2) % 3);
        cp_commit();

        compute_kc(ab, bb, 0);
        compute_kc(ab, bb, 1);
        if (pre) { stx(b ^ 1, 0); ldx(t + 1, 1); }
        compute_kc(ab, bb, 2);
        compute_kc(ab, bb, 3);
        if (pre) {
            stx(b ^ 1, 1);
            if (t + 2 < NT2) ldx(t + 2, 0);
        }

        cp_wait<1>();             // B(t+1) resident (own copies); barrier publishes
        __syncthreads();
    }

    // ---- sumsq: reduce over the 8 c-lanes per row ----
#pragma unroll
    for (int p = 0; p < 4; p++) {
        float v = ss[p];
        v += __shfl_down_sync(0xffffffffu, v, 4, 8);
        v += __shfl_down_sync(0xffffffffu, v, 2, 8);
        v += __shfl_down_sync(0xffffffffu, v, 1, 8);
        if (c == 0) g_scratch[s2][24][R + rr[p]] = v;
    }

    // ---- write dot partials: warp w owns rows R + w*16 .. +15 ----
    const int row0 = R + w * 16 + g4;
#pragma unroll
    for (int j = 0; j < 3; j++) {
        const int col = j * 8 + t4 * 2;
        g_scratch[s2][col    ][row0]     = acc[j][0];
        g_scratch[s2][col + 1][row0]     = acc[j][1];
        g_scratch[s2][col    ][row0 + 8] = acc[j][2];
        g_scratch[s2][col + 1][row0 + 8] = acc[j][3];
    }

    // ---- fused epilogue: 8th arriver per rowblock finishes rows R..R+127 ----
    __shared__ int s_last;
    __threadfence();
    __syncthreads();
    if (tid == 0) s_last = (atomicAdd(&g_cnt[rb], 1) == NSLOT - 1);
    __syncthreads();
    if (!s_last) return;

    if (tid < 128) {
        const int t = R + tid;

        float v[NACC];
#pragma unroll
        for (int i = 0; i < NACC; i++) {
            float a = 0.f;
#pragma unroll
            for (int sl = 0; sl < NSLOT; sl++)
                a += __ldcg(&g_scratch[sl][i][t]);
            v[i] = a;
        }

        const float rn = rsqrtf(v[24] * (1.0f / (float)ND) + 1e-8f);
        const float apre  = *apre_p;
        const float apost = *apost_p;
        const float ares  = *ares_p;

        float* outres  = out;                          // (T,4,4)
        float* outpre  = out + (size_t)T_LEN * 16;     // (T,4)
        float* outpost = out + (size_t)T_LEN * 20;     // (T,4)

#pragma unroll
        for (int k = 0; k < 4; k++) {
            const float z = apre * v[k] * rn + bpre[k];
            outpre[(size_t)t * 4 + k] = __fdividef(1.0f, 1.0f + __expf(-z));
        }
#pragma unroll
        for (int k = 0; k < 4; k++) {
            const float z = apost * v[4 + k] * rn + bpost[k];
            outpost[(size_t)t * 4 + k] = __fdividef(2.0f, 1.0f + __expf(-z));
        }

        float M[16];
#pragma unroll
        for (int i = 0; i < 16; i++)
            M[i] = __expf(ares * v[8 + i] * rn + bres[i]);

        for (int it = 0; it < 20; it++) {
#pragma unroll
            for (int a = 0; a < 4; a++) {
                const float r = __fdividef(1.0f,
                    M[4*a] + M[4*a+1] + M[4*a+2] + M[4*a+3]);
                M[4*a] *= r; M[4*a+1] *= r; M[4*a+2] *= r; M[4*a+3] *= r;
            }
#pragma unroll
            for (int b = 0; b < 4; b++) {
                const float r = __fdividef(1.0f,
                    M[b] + M[4+b] + M[8+b] + M[12+b]);
                M[b] *= r; M[4+b] *= r; M[8+b] *= r; M[12+b] *= r;
            }
        }
#pragma unroll
        for (int i = 0; i < 16; i++) outres[(size_t)t * 16 + i] = M[i];
    }

    __syncthreads();
    if (tid == 0) g_cnt[rb] = 0;    // reset for next graph replay
}

extern "C" void kernel_launch(void* const* d_in, const int* in_sizes, int n_in,
                              void* d_out, int out_size) {
    const float* stream = (const float*)d_in[0];
    const float* Wpre   = (const float*)d_in[1];
    const float* Wpost  = (const float*)d_in[2];
    const float* Wres   = (const float*)d_in[3];
    const float* bpre   = (const float*)d_in[4];
    const float* bpost  = (const float*)d_in[5];
    const float* bres   = (const float*)d_in[6];
    const float* apre   = (const float*)d_in[7];
    const float* apost  = (const float*)d_in[8];
    const float* ares   = (const float*)d_in[9];

    cudaFuncSetAttribute(mhc_main_mma,
                         cudaFuncAttributeMaxDynamicSharedMemorySize, SMEM_DYN);

    mhc_prep<<<192, 256>>>(Wpre, Wpost, Wres);
    mhc_main_mma<<<512, 256, SMEM_DYN>>>(stream, bpre, bpost, bres,
                                         apre, apost, ares, (float*)d_out);
}